// round 9
// baseline (speedup 1.0000x reference)
#include <cuda_runtime.h>
#include <cuda_bf16.h>
#include <cstdint>

#define NMAX 100000
#define NWORDS 50000
#define EMAX 500000
#define IN_DIM 256
#define OUT_DIM 128

// ---- scratch (static device globals; no allocation) ----
__device__ float    g_z[(size_t)NMAX * OUT_DIM];   // fc output z [N,128]
__device__ float    g_s1[NMAX];                    // z . a1
__device__ float    g_s2[NMAX];                    // z . a2
__device__ unsigned g_cnt[NWORDS];                 // per-dst edge counts
__device__ unsigned g_cnt2[NWORDS];                // scatter cursors
__device__ unsigned g_off[NWORDS + 1];             // CSR offsets
__device__ int      g_esrc[EMAX];                  // grouped edge src ids
__device__ float    g_eval[EMAX];                  // grouped edge scores
// pre-split B in swizzled tile layout: [kchunk][128 rows x 64 B]
__device__ __align__(16) uint8_t g_bhi[8 * 8192];
__device__ __align__(16) uint8_t g_blo[8 * 8192];

#define SCAN_BLOCKS ((NWORDS + 1023) / 1024)       // 49
__device__ unsigned g_bsum[SCAN_BLOCKS];
__device__ unsigned g_bar1;                        // grid barrier counters
__device__ unsigned g_bar2;

__device__ __forceinline__ uint32_t smem_u32(const void* p) {
    uint32_t a;
    asm("{ .reg .u64 t; cvta.to.shared.u64 t, %1; cvt.u32.u64 %0, t; }" : "=r"(a) : "l"(p));
    return a;
}
__device__ __forceinline__ void ldm_x4(uint32_t* r, uint32_t addr) {
    asm volatile("ldmatrix.sync.aligned.m8n8.x4.shared.b16 {%0,%1,%2,%3}, [%4];"
                 : "=r"(r[0]), "=r"(r[1]), "=r"(r[2]), "=r"(r[3]) : "r"(addr));
}
__device__ __forceinline__ void mma_bf16(float* c, const uint32_t* a, const uint32_t* b) {
    asm volatile(
        "mma.sync.aligned.m16n8k16.row.col.f32.bf16.bf16.f32 "
        "{%0,%1,%2,%3}, {%4,%5,%6,%7}, {%8,%9}, {%0,%1,%2,%3};"
        : "+f"(c[0]), "+f"(c[1]), "+f"(c[2]), "+f"(c[3])
        : "r"(a[0]), "r"(a[1]), "r"(a[2]), "r"(a[3]), "r"(b[0]), "r"(b[1]));
}
__device__ __forceinline__ uint32_t pack2(float a, float b) {
    __nv_bfloat162 t = __floats2bfloat162_rn(a, b);
    return *reinterpret_cast<uint32_t*>(&t);
}
// tile byte offset: row pitch 64B (32 bf16), 16B chunks xor-swizzled
__device__ __forceinline__ uint32_t tile_off(uint32_t row, uint32_t chunk) {
    return row * 64u + ((chunk ^ ((row >> 1) & 3u)) << 4);
}
// software grid barrier (all blocks co-resident: 49 blocks << 148 SMs)
__device__ __forceinline__ void grid_bar(unsigned* ctr, unsigned target) {
    __syncthreads();
    __threadfence();
    if (threadIdx.x == 0) {
        unsigned t = atomicAdd(ctr, 1u) + 1u;
        if (t < target)
            while (atomicAdd(ctr, 0u) < target) { }
    }
    __syncthreads();
}

// ---- init counters + score accumulators + one-time B split-convert ----
__global__ __launch_bounds__(256) void init_kernel(const float* __restrict__ B, int M) {
    int i = blockIdx.x * blockDim.x + threadIdx.x;
    if (i == 0) { g_bar1 = 0u; g_bar2 = 0u; }
    if (i < NWORDS) { g_cnt[i] = 0u; g_cnt2[i] = 0u; }
    if (i < M) { g_s1[i] = 0.0f; g_s2[i] = 0.0f; }
    if (i < 128 * 256) {
        int row = i >> 8, col = i & 255;
        int kc = col >> 5, c = col & 31;
        float v = B[i];
        __nv_bfloat16 hi = __float2bfloat16(v);
        __nv_bfloat16 lo = __float2bfloat16(v - __bfloat162float(hi));
        uint32_t off = (uint32_t)kc * 8192u + tile_off((uint32_t)row, (uint32_t)(c >> 3)) + (c & 7) * 2;
        *(__nv_bfloat16*)(g_bhi + off) = hi;
        *(__nv_bfloat16*)(g_blo + off) = lo;
    }
}

// ==========================================================================
// bf16 split-GEMM via mma.sync (hh + hl + lh), fused s1/s2 epilogue.
// ==========================================================================
__global__ void __launch_bounds__(256, 2)
gemm_mma(const float* __restrict__ A, const float* __restrict__ Wa, int M)
{
    __shared__ __align__(128) uint8_t sAhi[128 * 64];
    __shared__ __align__(128) uint8_t sAlo[128 * 64];
    __shared__ __align__(128) uint8_t sBhi[128 * 64];
    __shared__ __align__(128) uint8_t sBlo[128 * 64];

    const int tid  = threadIdx.x;
    const int lane = tid & 31;
    const int w    = tid >> 5;
    const int wm   = w & 3;
    const int wn   = w >> 2;
    const int block_m = blockIdx.x * 128;
    int rows_valid = M - block_m; if (rows_valid > 128) rows_valid = 128;

    const uint32_t uAhi = smem_u32(sAhi), uAlo = smem_u32(sAlo);
    const uint32_t uBhi = smem_u32(sBhi), uBlo = smem_u32(sBlo);

    const uint32_t a_row  = wm * 32u + (lane & 15);
    const uint32_t a_half = (uint32_t)lane >> 4;
    const uint32_t a_sw   = (a_row >> 1) & 3u;
    const uint32_t b_row  = wn * 64u + (lane & 7) + (((uint32_t)lane >> 4) << 3);
    const uint32_t b_half = ((uint32_t)lane >> 3) & 1u;
    const uint32_t b_sw   = (b_row >> 1) & 3u;

    const int r0 = tid >> 2,         c0 = tid & 3;
    const int r1 = (tid + 256) >> 2, c1 = (tid + 256) & 3;
    const uint32_t doff0 = tile_off((uint32_t)r0, (uint32_t)c0);
    const uint32_t doff1 = tile_off((uint32_t)r1, (uint32_t)c1);

    float acc[2][8][4];
#pragma unroll
    for (int i = 0; i < 2; i++)
#pragma unroll
        for (int j = 0; j < 8; j++)
#pragma unroll
            for (int r = 0; r < 4; r++) acc[i][j][r] = 0.0f;

    float4 pv[4];
    {
        pv[0] = pv[1] = pv[2] = pv[3] = make_float4(0.f, 0.f, 0.f, 0.f);
        if (r0 < rows_valid) {
            const float* p = &A[(size_t)(block_m + r0) * IN_DIM + c0 * 8];
            pv[0] = *(const float4*)p; pv[1] = *(const float4*)(p + 4);
        }
        if (r1 < rows_valid) {
            const float* p = &A[(size_t)(block_m + r1) * IN_DIM + c1 * 8];
            pv[2] = *(const float4*)p; pv[3] = *(const float4*)(p + 4);
        }
    }

    for (int kc = 0; kc < IN_DIM / 32; kc++) {
#pragma unroll
        for (int it = 0; it < 2; it++) {
            float4 v0 = pv[it * 2], v1 = pv[it * 2 + 1];
            uint32_t h0 = pack2(v0.x, v0.y), h1 = pack2(v0.z, v0.w);
            uint32_t h2 = pack2(v1.x, v1.y), h3 = pack2(v1.z, v1.w);
            __nv_bfloat162* q;
            q = (__nv_bfloat162*)&h0;
            uint32_t l0 = pack2(v0.x - __bfloat162float(q->x), v0.y - __bfloat162float(q->y));
            q = (__nv_bfloat162*)&h1;
            uint32_t l1 = pack2(v0.z - __bfloat162float(q->x), v0.w - __bfloat162float(q->y));
            q = (__nv_bfloat162*)&h2;
            uint32_t l2 = pack2(v1.x - __bfloat162float(q->x), v1.y - __bfloat162float(q->y));
            q = (__nv_bfloat162*)&h3;
            uint32_t l3 = pack2(v1.z - __bfloat162float(q->x), v1.w - __bfloat162float(q->y));
            uint32_t doff = it ? doff1 : doff0;
            *(uint4*)(sAhi + doff) = make_uint4(h0, h1, h2, h3);
            *(uint4*)(sAlo + doff) = make_uint4(l0, l1, l2, l3);
        }
        {
            const uint4* bh = (const uint4*)(g_bhi + kc * 8192);
            const uint4* bl = (const uint4*)(g_blo + kc * 8192);
            uint4* dh = (uint4*)sBhi;
            uint4* dl = (uint4*)sBlo;
            dh[tid]       = bh[tid];
            dh[tid + 256] = bh[tid + 256];
            dl[tid]       = bl[tid];
            dl[tid + 256] = bl[tid + 256];
        }
        __syncthreads();

        if (kc + 1 < IN_DIM / 32) {
            const int k0n = (kc + 1) * 32;
            pv[0] = pv[1] = pv[2] = pv[3] = make_float4(0.f, 0.f, 0.f, 0.f);
            if (r0 < rows_valid) {
                const float* p = &A[(size_t)(block_m + r0) * IN_DIM + k0n + c0 * 8];
                pv[0] = *(const float4*)p; pv[1] = *(const float4*)(p + 4);
            }
            if (r1 < rows_valid) {
                const float* p = &A[(size_t)(block_m + r1) * IN_DIM + k0n + c1 * 8];
                pv[2] = *(const float4*)p; pv[3] = *(const float4*)(p + 4);
            }
        }

#pragma unroll
        for (int ks = 0; ks < 2; ks++) {
            uint32_t ahi[2][4], alo[2][4], bb[4][4];
#pragma unroll
            for (int i = 0; i < 2; i++) {
                uint32_t row = a_row + i * 16u;
                uint32_t chunk = (uint32_t)(ks * 2) + a_half;
                uint32_t o = row * 64u + ((chunk ^ a_sw) << 4);
                ldm_x4(ahi[i], uAhi + o);
                ldm_x4(alo[i], uAlo + o);
            }
#pragma unroll
            for (int j = 0; j < 4; j++) {
                uint32_t row = b_row + j * 16u;
                uint32_t chunk = (uint32_t)(ks * 2) + b_half;
                uint32_t o = row * 64u + ((chunk ^ b_sw) << 4);
                ldm_x4(bb[j], uBhi + o);
            }
#pragma unroll
            for (int i = 0; i < 2; i++)
#pragma unroll
                for (int jf = 0; jf < 8; jf++) {
                    mma_bf16(acc[i][jf], ahi[i], &bb[jf >> 1][(jf & 1) * 2]);
                    mma_bf16(acc[i][jf], alo[i], &bb[jf >> 1][(jf & 1) * 2]);
                }
#pragma unroll
            for (int j = 0; j < 4; j++) {
                uint32_t row = b_row + j * 16u;
                uint32_t chunk = (uint32_t)(ks * 2) + b_half;
                uint32_t o = row * 64u + ((chunk ^ b_sw) << 4);
                ldm_x4(bb[j], uBlo + o);
            }
#pragma unroll
            for (int i = 0; i < 2; i++)
#pragma unroll
                for (int jf = 0; jf < 8; jf++)
                    mma_bf16(acc[i][jf], ahi[i], &bb[jf >> 1][(jf & 1) * 2]);
        }
        __syncthreads();
    }

    float rs1[4] = {0.f, 0.f, 0.f, 0.f}, rs2[4] = {0.f, 0.f, 0.f, 0.f};
#pragma unroll
    for (int i = 0; i < 2; i++)
#pragma unroll
        for (int jf = 0; jf < 8; jf++) {
            int n0 = wn * 64 + jf * 8 + (lane & 3) * 2;
            float a1x = __ldg(&Wa[n0]),            a1y = __ldg(&Wa[n0 + 1]);
            float a2x = __ldg(&Wa[OUT_DIM + n0]),  a2y = __ldg(&Wa[OUT_DIM + n0 + 1]);
#pragma unroll
            for (int hh = 0; hh < 2; hh++) {
                float v0 = acc[i][jf][hh * 2], v1 = acc[i][jf][hh * 2 + 1];
                int m = block_m + wm * 32 + i * 16 + hh * 8 + (lane >> 2);
                if (m < M)
                    *(float2*)&g_z[(size_t)m * OUT_DIM + n0] = make_float2(v0, v1);
                rs1[i * 2 + hh] += v0 * a1x + v1 * a1y;
                rs2[i * 2 + hh] += v0 * a2x + v1 * a2y;
            }
        }
#pragma unroll
    for (int k = 0; k < 4; k++) {
        rs1[k] += __shfl_xor_sync(0xffffffffu, rs1[k], 1);
        rs1[k] += __shfl_xor_sync(0xffffffffu, rs1[k], 2);
        rs2[k] += __shfl_xor_sync(0xffffffffu, rs2[k], 1);
        rs2[k] += __shfl_xor_sync(0xffffffffu, rs2[k], 2);
    }
    if ((lane & 3) == 0) {
#pragma unroll
        for (int k = 0; k < 4; k++) {
            int m = block_m + wm * 32 + (k >> 1) * 16 + (k & 1) * 8 + (lane >> 2);
            if (m < M) {
                atomicAdd(&g_s1[m], rs1[k]);
                atomicAdd(&g_s2[m], rs2[k]);
            }
        }
    }
}

// ==========================================================================
// fused hist + scan: 49 blocks x 1024, software grid barriers (co-resident)
// ==========================================================================
__global__ __launch_bounds__(1024) void hist_scan_kernel(const int* __restrict__ dst, int E) {
    const int tid = threadIdx.x, lane = tid & 31, wid = tid >> 5;
    const int gid = blockIdx.x * 1024 + tid;
    const int nth = SCAN_BLOCKS * 1024;

    // ---- phase 1: histogram (grid-strided, 4 edges per step) ----
    for (int base = gid * 4; base + 4 <= E; base += nth * 4) {
        int4 d = *(const int4*)&dst[base];
        atomicAdd(&g_cnt[d.x], 1u); atomicAdd(&g_cnt[d.y], 1u);
        atomicAdd(&g_cnt[d.z], 1u); atomicAdd(&g_cnt[d.w], 1u);
    }
    if (gid == 0)
        for (int i = (E & ~3); i < E; i++) atomicAdd(&g_cnt[dst[i]], 1u);

    grid_bar(&g_bar1, SCAN_BLOCKS);

    // ---- phase 2a: per-block tile reduction ----
    __shared__ unsigned ws[32];
    __shared__ unsigned s_boff;
    int i = blockIdx.x * 1024 + tid;
    unsigned x = (i < NWORDS) ? g_cnt[i] : 0u;
    {
        unsigned r = x;
#pragma unroll
        for (int o = 16; o > 0; o >>= 1) r += __shfl_xor_sync(0xffffffffu, r, o);
        if (lane == 0) ws[wid] = r;
        __syncthreads();
        if (wid == 0) {
            unsigned s = ws[lane];
#pragma unroll
            for (int o = 16; o > 0; o >>= 1) s += __shfl_xor_sync(0xffffffffu, s, o);
            if (lane == 0) g_bsum[blockIdx.x] = s;
        }
    }

    grid_bar(&g_bar2, SCAN_BLOCKS);

    // ---- phase 2b: warp 0 scans block sums; block scans tile; write ----
    if (wid == 0) {
        unsigned acc = 0u;
#pragma unroll
        for (int seg = 0; seg < (SCAN_BLOCKS + 31) / 32; seg++) {
            int j = seg * 32 + lane;
            unsigned v = (j < SCAN_BLOCKS) ? g_bsum[j] : 0u;
            unsigned inc = v;
#pragma unroll
            for (int o = 1; o < 32; o <<= 1) {
                unsigned y = __shfl_up_sync(0xffffffffu, inc, o);
                if (lane >= o) inc += y;
            }
            if (j == (int)blockIdx.x) s_boff = acc + inc - v;
            acc += __shfl_sync(0xffffffffu, inc, 31);
        }
    }
    __syncthreads();

    unsigned inc = x;
#pragma unroll
    for (int o = 1; o < 32; o <<= 1) {
        unsigned y = __shfl_up_sync(0xffffffffu, inc, o);
        if (lane >= o) inc += y;
    }
    if (lane == 31) ws[wid] = inc;
    __syncthreads();
    if (wid == 0) {
        unsigned s = ws[lane];
#pragma unroll
        for (int o = 1; o < 32; o <<= 1) {
            unsigned y = __shfl_up_sync(0xffffffffu, s, o);
            if (lane >= o) s += y;
        }
        ws[lane] = s;
    }
    __syncthreads();
    unsigned val = inc + (wid > 0 ? ws[wid - 1] : 0u) + s_boff;
    if (i < NWORDS) g_off[i + 1] = val;
    if (i == 0) g_off[0] = 0u;
}

// ---- build grouped edge arrays: 4 edges/thread, vectorized loads ----
__global__ __launch_bounds__(256) void build_kernel(
    const int* __restrict__ src, const int* __restrict__ dst, int E)
{
    int base = (blockIdx.x * blockDim.x + threadIdx.x) * 4;
    if (base + 4 <= E) {
        int4 sv = *(const int4*)&src[base];
        int4 dv = *(const int4*)&dst[base];
        float a1 = g_s1[sv.x], a2 = g_s1[sv.y], a3 = g_s1[sv.z], a4 = g_s1[sv.w];
        float b1 = g_s2[dv.x], b2 = g_s2[dv.y], b3 = g_s2[dv.z], b4 = g_s2[dv.w];
        unsigned o1 = g_off[dv.x], o2 = g_off[dv.y], o3 = g_off[dv.z], o4 = g_off[dv.w];
        float e1 = a1 + b1, e2 = a2 + b2, e3 = a3 + b3, e4 = a4 + b4;
        e1 = (e1 > 0.f) ? e1 : 0.01f * e1; if (e1 == 0.f) e1 = -1000.f;
        e2 = (e2 > 0.f) ? e2 : 0.01f * e2; if (e2 == 0.f) e2 = -1000.f;
        e3 = (e3 > 0.f) ? e3 : 0.01f * e3; if (e3 == 0.f) e3 = -1000.f;
        e4 = (e4 > 0.f) ? e4 : 0.01f * e4; if (e4 == 0.f) e4 = -1000.f;
        unsigned p1 = o1 + atomicAdd(&g_cnt2[dv.x], 1u);
        unsigned p2 = o2 + atomicAdd(&g_cnt2[dv.y], 1u);
        unsigned p3 = o3 + atomicAdd(&g_cnt2[dv.z], 1u);
        unsigned p4 = o4 + atomicAdd(&g_cnt2[dv.w], 1u);
        g_esrc[p1] = sv.x; g_eval[p1] = e1;
        g_esrc[p2] = sv.y; g_eval[p2] = e2;
        g_esrc[p3] = sv.z; g_eval[p3] = e3;
        g_esrc[p4] = sv.w; g_eval[p4] = e4;
    } else {
        for (int i = base; i < E; i++) {
            int s = src[i], d = dst[i];
            float e = g_s1[s] + g_s2[d];
            e = (e > 0.0f) ? e : 0.01f * e;
            if (e == 0.0f) e = -1000.0f;
            unsigned pos = g_off[d] + atomicAdd(&g_cnt2[d], 1u);
            g_esrc[pos] = s;
            g_eval[pos] = e;
        }
    }
}

// ---- aggregate: warp per dst; softmax + weighted sum, single write ----
__global__ __launch_bounds__(256) void aggregate_kernel(float* __restrict__ out) {
    int d    = (blockIdx.x * blockDim.x + threadIdx.x) >> 5;
    int lane = threadIdx.x & 31;
    if (d >= NWORDS) return;
    int b = (int)g_off[d], eend = (int)g_off[d + 1];

    float mx = -1e30f;
    for (int i = b + lane; i < eend; i += 32) mx = fmaxf(mx, g_eval[i]);
#pragma unroll
    for (int o = 16; o > 0; o >>= 1)
        mx = fmaxf(mx, __shfl_xor_sync(0xffffffffu, mx, o));

    float4 acc = make_float4(0.f, 0.f, 0.f, 0.f);
    float denom = 0.f;
    int i = b;
    for (; i + 3 < eend; i += 4) {
        float e0 = g_eval[i],     e1 = g_eval[i + 1];
        float e2 = g_eval[i + 2], e3 = g_eval[i + 3];
        int   s0 = g_esrc[i],     s1 = g_esrc[i + 1];
        int   s2 = g_esrc[i + 2], s3 = g_esrc[i + 3];
        float4 z0 = *(const float4*)&g_z[(size_t)s0 * OUT_DIM + lane * 4];
        float4 z1 = *(const float4*)&g_z[(size_t)s1 * OUT_DIM + lane * 4];
        float4 z2 = *(const float4*)&g_z[(size_t)s2 * OUT_DIM + lane * 4];
        float4 z3 = *(const float4*)&g_z[(size_t)s3 * OUT_DIM + lane * 4];
        float x0 = __expf(e0 - mx), x1 = __expf(e1 - mx);
        float x2 = __expf(e2 - mx), x3 = __expf(e3 - mx);
        denom += (x0 + x1) + (x2 + x3);
        acc.x += x0 * z0.x + x1 * z1.x + x2 * z2.x + x3 * z3.x;
        acc.y += x0 * z0.y + x1 * z1.y + x2 * z2.y + x3 * z3.y;
        acc.z += x0 * z0.z + x1 * z1.z + x2 * z2.z + x3 * z3.z;
        acc.w += x0 * z0.w + x1 * z1.w + x2 * z2.w + x3 * z3.w;
    }
    for (; i < eend; i++) {
        float e0 = g_eval[i];
        int   s0 = g_esrc[i];
        float4 z0 = *(const float4*)&g_z[(size_t)s0 * OUT_DIM + lane * 4];
        float x0 = __expf(e0 - mx);
        denom += x0;
        acc.x += x0 * z0.x; acc.y += x0 * z0.y;
        acc.z += x0 * z0.z; acc.w += x0 * z0.w;
    }
    float inv = (eend > b) ? 1.0f / denom : 0.0f;
    *(float4*)&out[(size_t)d * OUT_DIM + lane * 4] =
        make_float4(acc.x * inv, acc.y * inv, acc.z * inv, acc.w * inv);
}

extern "C" void kernel_launch(void* const* d_in, const int* in_sizes, int n_in,
                              void* d_out, int out_size) {
    const float* h   = (const float*)d_in[0];
    const int*   src = (const int*)d_in[1];
    const int*   dst = (const int*)d_in[2];
    const float* Wfc = (const float*)d_in[3];
    const float* Wa  = (const float*)d_in[4];
    float* out = (float*)d_out;

    int M = in_sizes[0] / IN_DIM;   // 100000
    int E = in_sizes[1];            // 500000

    init_kernel<<<(NMAX + 255) / 256, 256>>>(Wfc, M);
    hist_scan_kernel<<<SCAN_BLOCKS, 1024>>>(dst, E);
    gemm_mma<<<(M + 127) / 128, 256>>>(h, Wa, M);
    build_kernel<<<(E + 4 * 256 - 1) / (4 * 256), 256>>>(src, dst, E);
    aggregate_kernel<<<((NWORDS * 32) + 255) / 256, 256>>>(out);
}

// round 10
// speedup vs baseline: 1.2979x; 1.2979x over previous
#include <cuda_runtime.h>
#include <cuda_bf16.h>
#include <cstdint>

#define NMAX 100000
#define NWORDS 50000
#define EMAX 500000
#define IN_DIM 256
#define OUT_DIM 128

// ---- scratch (static device globals; no allocation) ----
__device__ float    g_z[(size_t)NMAX * OUT_DIM];   // fc output z [N,128]
__device__ float    g_s1[NMAX];                    // z . a1
__device__ float    g_s2[NMAX];                    // z . a2
__device__ unsigned g_cnt[NWORDS];                 // per-dst edge counts
__device__ unsigned g_cnt2[NWORDS];                // scatter cursors
__device__ unsigned g_off[NWORDS + 1];             // CSR offsets
__device__ int      g_esrc[EMAX];                  // grouped edge src ids
__device__ float    g_eval[EMAX];                  // grouped edge scores
// pre-split B in swizzled tile layout: [kchunk][128 rows x 64 B]
__device__ __align__(16) uint8_t g_bhi[8 * 8192];
__device__ __align__(16) uint8_t g_blo[8 * 8192];

#define SCAN_BLOCKS ((NWORDS + 1023) / 1024)       // 49
__device__ unsigned g_bsum[SCAN_BLOCKS];

__device__ __forceinline__ uint32_t smem_u32(const void* p) {
    uint32_t a;
    asm("{ .reg .u64 t; cvta.to.shared.u64 t, %1; cvt.u32.u64 %0, t; }" : "=r"(a) : "l"(p));
    return a;
}
__device__ __forceinline__ void ldm_x4(uint32_t* r, uint32_t addr) {
    asm volatile("ldmatrix.sync.aligned.m8n8.x4.shared.b16 {%0,%1,%2,%3}, [%4];"
                 : "=r"(r[0]), "=r"(r[1]), "=r"(r[2]), "=r"(r[3]) : "r"(addr));
}
__device__ __forceinline__ void mma_bf16(float* c, const uint32_t* a, const uint32_t* b) {
    asm volatile(
        "mma.sync.aligned.m16n8k16.row.col.f32.bf16.bf16.f32 "
        "{%0,%1,%2,%3}, {%4,%5,%6,%7}, {%8,%9}, {%0,%1,%2,%3};"
        : "+f"(c[0]), "+f"(c[1]), "+f"(c[2]), "+f"(c[3])
        : "r"(a[0]), "r"(a[1]), "r"(a[2]), "r"(a[3]), "r"(b[0]), "r"(b[1]));
}
__device__ __forceinline__ uint32_t pack2(float a, float b) {
    __nv_bfloat162 t = __floats2bfloat162_rn(a, b);
    return *reinterpret_cast<uint32_t*>(&t);
}
// tile byte offset: row pitch 64B (32 bf16), 16B chunks xor-swizzled
__device__ __forceinline__ uint32_t tile_off(uint32_t row, uint32_t chunk) {
    return row * 64u + ((chunk ^ ((row >> 1) & 3u)) << 4);
}

// ---- init counters + score accumulators + one-time B split-convert ----
__global__ __launch_bounds__(256) void init_kernel(const float* __restrict__ B, int M) {
    int i = blockIdx.x * blockDim.x + threadIdx.x;
    if (i < NWORDS) { g_cnt[i] = 0u; g_cnt2[i] = 0u; }
    if (i < M) { g_s1[i] = 0.0f; g_s2[i] = 0.0f; }
    if (i < 128 * 256) {
        int row = i >> 8, col = i & 255;
        int kc = col >> 5, c = col & 31;
        float v = B[i];
        __nv_bfloat16 hi = __float2bfloat16(v);
        __nv_bfloat16 lo = __float2bfloat16(v - __bfloat162float(hi));
        uint32_t off = (uint32_t)kc * 8192u + tile_off((uint32_t)row, (uint32_t)(c >> 3)) + (c & 7) * 2;
        *(__nv_bfloat16*)(g_bhi + off) = hi;
        *(__nv_bfloat16*)(g_blo + off) = lo;
    }
}

// ==========================================================================
// bf16 split-GEMM via mma.sync (hh + hl + lh), fused s1/s2 epilogue.
// ==========================================================================
__global__ void __launch_bounds__(256, 2)
gemm_mma(const float* __restrict__ A, const float* __restrict__ Wa, int M)
{
    __shared__ __align__(128) uint8_t sAhi[128 * 64];
    __shared__ __align__(128) uint8_t sAlo[128 * 64];
    __shared__ __align__(128) uint8_t sBhi[128 * 64];
    __shared__ __align__(128) uint8_t sBlo[128 * 64];

    const int tid  = threadIdx.x;
    const int lane = tid & 31;
    const int w    = tid >> 5;
    const int wm   = w & 3;
    const int wn   = w >> 2;
    const int block_m = blockIdx.x * 128;
    int rows_valid = M - block_m; if (rows_valid > 128) rows_valid = 128;

    const uint32_t uAhi = smem_u32(sAhi), uAlo = smem_u32(sAlo);
    const uint32_t uBhi = smem_u32(sBhi), uBlo = smem_u32(sBlo);

    const uint32_t a_row  = wm * 32u + (lane & 15);
    const uint32_t a_half = (uint32_t)lane >> 4;
    const uint32_t a_sw   = (a_row >> 1) & 3u;
    const uint32_t b_row  = wn * 64u + (lane & 7) + (((uint32_t)lane >> 4) << 3);
    const uint32_t b_half = ((uint32_t)lane >> 3) & 1u;
    const uint32_t b_sw   = (b_row >> 1) & 3u;

    const int r0 = tid >> 2,         c0 = tid & 3;
    const int r1 = (tid + 256) >> 2, c1 = (tid + 256) & 3;
    const uint32_t doff0 = tile_off((uint32_t)r0, (uint32_t)c0);
    const uint32_t doff1 = tile_off((uint32_t)r1, (uint32_t)c1);

    float acc[2][8][4];
#pragma unroll
    for (int i = 0; i < 2; i++)
#pragma unroll
        for (int j = 0; j < 8; j++)
#pragma unroll
            for (int r = 0; r < 4; r++) acc[i][j][r] = 0.0f;

    float4 pv[4];
    {
        pv[0] = pv[1] = pv[2] = pv[3] = make_float4(0.f, 0.f, 0.f, 0.f);
        if (r0 < rows_valid) {
            const float* p = &A[(size_t)(block_m + r0) * IN_DIM + c0 * 8];
            pv[0] = *(const float4*)p; pv[1] = *(const float4*)(p + 4);
        }
        if (r1 < rows_valid) {
            const float* p = &A[(size_t)(block_m + r1) * IN_DIM + c1 * 8];
            pv[2] = *(const float4*)p; pv[3] = *(const float4*)(p + 4);
        }
    }

    for (int kc = 0; kc < IN_DIM / 32; kc++) {
#pragma unroll
        for (int it = 0; it < 2; it++) {
            float4 v0 = pv[it * 2], v1 = pv[it * 2 + 1];
            uint32_t h0 = pack2(v0.x, v0.y), h1 = pack2(v0.z, v0.w);
            uint32_t h2 = pack2(v1.x, v1.y), h3 = pack2(v1.z, v1.w);
            __nv_bfloat162* q;
            q = (__nv_bfloat162*)&h0;
            uint32_t l0 = pack2(v0.x - __bfloat162float(q->x), v0.y - __bfloat162float(q->y));
            q = (__nv_bfloat162*)&h1;
            uint32_t l1 = pack2(v0.z - __bfloat162float(q->x), v0.w - __bfloat162float(q->y));
            q = (__nv_bfloat162*)&h2;
            uint32_t l2 = pack2(v1.x - __bfloat162float(q->x), v1.y - __bfloat162float(q->y));
            q = (__nv_bfloat162*)&h3;
            uint32_t l3 = pack2(v1.z - __bfloat162float(q->x), v1.w - __bfloat162float(q->y));
            uint32_t doff = it ? doff1 : doff0;
            *(uint4*)(sAhi + doff) = make_uint4(h0, h1, h2, h3);
            *(uint4*)(sAlo + doff) = make_uint4(l0, l1, l2, l3);
        }
        {
            const uint4* bh = (const uint4*)(g_bhi + kc * 8192);
            const uint4* bl = (const uint4*)(g_blo + kc * 8192);
            uint4* dh = (uint4*)sBhi;
            uint4* dl = (uint4*)sBlo;
            dh[tid]       = bh[tid];
            dh[tid + 256] = bh[tid + 256];
            dl[tid]       = bl[tid];
            dl[tid + 256] = bl[tid + 256];
        }
        __syncthreads();

        if (kc + 1 < IN_DIM / 32) {
            const int k0n = (kc + 1) * 32;
            pv[0] = pv[1] = pv[2] = pv[3] = make_float4(0.f, 0.f, 0.f, 0.f);
            if (r0 < rows_valid) {
                const float* p = &A[(size_t)(block_m + r0) * IN_DIM + k0n + c0 * 8];
                pv[0] = *(const float4*)p; pv[1] = *(const float4*)(p + 4);
            }
            if (r1 < rows_valid) {
                const float* p = &A[(size_t)(block_m + r1) * IN_DIM + k0n + c1 * 8];
                pv[2] = *(const float4*)p; pv[3] = *(const float4*)(p + 4);
            }
        }

#pragma unroll
        for (int ks = 0; ks < 2; ks++) {
            uint32_t ahi[2][4], alo[2][4], bb[4][4];
#pragma unroll
            for (int i = 0; i < 2; i++) {
                uint32_t row = a_row + i * 16u;
                uint32_t chunk = (uint32_t)(ks * 2) + a_half;
                uint32_t o = row * 64u + ((chunk ^ a_sw) << 4);
                ldm_x4(ahi[i], uAhi + o);
                ldm_x4(alo[i], uAlo + o);
            }
#pragma unroll
            for (int j = 0; j < 4; j++) {
                uint32_t row = b_row + j * 16u;
                uint32_t chunk = (uint32_t)(ks * 2) + b_half;
                uint32_t o = row * 64u + ((chunk ^ b_sw) << 4);
                ldm_x4(bb[j], uBhi + o);
            }
#pragma unroll
            for (int i = 0; i < 2; i++)
#pragma unroll
                for (int jf = 0; jf < 8; jf++) {
                    mma_bf16(acc[i][jf], ahi[i], &bb[jf >> 1][(jf & 1) * 2]);
                    mma_bf16(acc[i][jf], alo[i], &bb[jf >> 1][(jf & 1) * 2]);
                }
#pragma unroll
            for (int j = 0; j < 4; j++) {
                uint32_t row = b_row + j * 16u;
                uint32_t chunk = (uint32_t)(ks * 2) + b_half;
                uint32_t o = row * 64u + ((chunk ^ b_sw) << 4);
                ldm_x4(bb[j], uBlo + o);
            }
#pragma unroll
            for (int i = 0; i < 2; i++)
#pragma unroll
                for (int jf = 0; jf < 8; jf++)
                    mma_bf16(acc[i][jf], ahi[i], &bb[jf >> 1][(jf & 1) * 2]);
        }
        __syncthreads();
    }

    float rs1[4] = {0.f, 0.f, 0.f, 0.f}, rs2[4] = {0.f, 0.f, 0.f, 0.f};
#pragma unroll
    for (int i = 0; i < 2; i++)
#pragma unroll
        for (int jf = 0; jf < 8; jf++) {
            int n0 = wn * 64 + jf * 8 + (lane & 3) * 2;
            float a1x = __ldg(&Wa[n0]),            a1y = __ldg(&Wa[n0 + 1]);
            float a2x = __ldg(&Wa[OUT_DIM + n0]),  a2y = __ldg(&Wa[OUT_DIM + n0 + 1]);
#pragma unroll
            for (int hh = 0; hh < 2; hh++) {
                float v0 = acc[i][jf][hh * 2], v1 = acc[i][jf][hh * 2 + 1];
                int m = block_m + wm * 32 + i * 16 + hh * 8 + (lane >> 2);
                if (m < M)
                    *(float2*)&g_z[(size_t)m * OUT_DIM + n0] = make_float2(v0, v1);
                rs1[i * 2 + hh] += v0 * a1x + v1 * a1y;
                rs2[i * 2 + hh] += v0 * a2x + v1 * a2y;
            }
        }
#pragma unroll
    for (int k = 0; k < 4; k++) {
        rs1[k] += __shfl_xor_sync(0xffffffffu, rs1[k], 1);
        rs1[k] += __shfl_xor_sync(0xffffffffu, rs1[k], 2);
        rs2[k] += __shfl_xor_sync(0xffffffffu, rs2[k], 1);
        rs2[k] += __shfl_xor_sync(0xffffffffu, rs2[k], 2);
    }
    if ((lane & 3) == 0) {
#pragma unroll
        for (int k = 0; k < 4; k++) {
            int m = block_m + wm * 32 + (k >> 1) * 16 + (k & 1) * 8 + (lane >> 2);
            if (m < M) {
                atomicAdd(&g_s1[m], rs1[k]);
                atomicAdd(&g_s2[m], rs2[k]);
            }
        }
    }
}

// ---- histogram of dst: 8 edges per thread (vectorized, MLP=2x int4) ----
__global__ __launch_bounds__(256) void hist_kernel(const int* __restrict__ dst, int E) {
    int base = (blockIdx.x * blockDim.x + threadIdx.x) * 8;
    if (base + 8 <= E) {
        int4 d0 = *(const int4*)&dst[base];
        int4 d1 = *(const int4*)&dst[base + 4];
        atomicAdd(&g_cnt[d0.x], 1u); atomicAdd(&g_cnt[d0.y], 1u);
        atomicAdd(&g_cnt[d0.z], 1u); atomicAdd(&g_cnt[d0.w], 1u);
        atomicAdd(&g_cnt[d1.x], 1u); atomicAdd(&g_cnt[d1.y], 1u);
        atomicAdd(&g_cnt[d1.z], 1u); atomicAdd(&g_cnt[d1.w], 1u);
    } else {
        for (int i = base; i < E; i++) atomicAdd(&g_cnt[dst[i]], 1u);
    }
}

// ---- scan phase 1: per-block tile reduction (coalesced) ----
__global__ __launch_bounds__(1024) void scan_part1() {
    __shared__ unsigned ws[32];
    const int tid = threadIdx.x, lane = tid & 31, wid = tid >> 5;
    int i = blockIdx.x * 1024 + tid;
    unsigned x = (i < NWORDS) ? g_cnt[i] : 0u;
#pragma unroll
    for (int o = 16; o > 0; o >>= 1) x += __shfl_xor_sync(0xffffffffu, x, o);
    if (lane == 0) ws[wid] = x;
    __syncthreads();
    if (wid == 0) {
        unsigned s = ws[lane];
#pragma unroll
        for (int o = 16; o > 0; o >>= 1) s += __shfl_xor_sync(0xffffffffu, s, o);
        if (lane == 0) g_bsum[blockIdx.x] = s;
    }
}

// ---- scan phase 2 (fused): each block scans block sums + its tile ----
__global__ __launch_bounds__(1024) void scan_part3() {
    __shared__ unsigned ws[32];
    __shared__ unsigned s_boff;
    const int tid = threadIdx.x, lane = tid & 31, wid = tid >> 5;

    if (wid == 0) {
        unsigned acc = 0u;
#pragma unroll
        for (int seg = 0; seg < (SCAN_BLOCKS + 31) / 32; seg++) {
            int j = seg * 32 + lane;
            unsigned v = (j < SCAN_BLOCKS) ? g_bsum[j] : 0u;
            unsigned inc = v;
#pragma unroll
            for (int o = 1; o < 32; o <<= 1) {
                unsigned y = __shfl_up_sync(0xffffffffu, inc, o);
                if (lane >= o) inc += y;
            }
            if (j == (int)blockIdx.x) s_boff = acc + inc - v;
            acc += __shfl_sync(0xffffffffu, inc, 31);
        }
    }

    int i = blockIdx.x * 1024 + tid;
    unsigned x = (i < NWORDS) ? g_cnt[i] : 0u;
    unsigned inc = x;
#pragma unroll
    for (int o = 1; o < 32; o <<= 1) {
        unsigned y = __shfl_up_sync(0xffffffffu, inc, o);
        if (lane >= o) inc += y;
    }
    if (lane == 31) ws[wid] = inc;
    __syncthreads();
    if (wid == 0) {
        unsigned s = ws[lane];
#pragma unroll
        for (int o = 1; o < 32; o <<= 1) {
            unsigned y = __shfl_up_sync(0xffffffffu, s, o);
            if (lane >= o) s += y;
        }
        ws[lane] = s;
    }
    __syncthreads();
    unsigned val = inc + (wid > 0 ? ws[wid - 1] : 0u) + s_boff;
    if (i < NWORDS) g_off[i + 1] = val;
    if (i == 0) g_off[0] = 0u;
}

// ---- build grouped edge arrays: 1 edge/thread (occupancy hides latency) ----
__global__ __launch_bounds__(256) void build_kernel(
    const int* __restrict__ src, const int* __restrict__ dst, int E)
{
    int i = blockIdx.x * blockDim.x + threadIdx.x;
    if (i >= E) return;
    int s = src[i], d = dst[i];
    float e = g_s1[s] + g_s2[d];
    e = (e > 0.0f) ? e : 0.01f * e;      // leaky_relu(0.01)
    if (e == 0.0f) e = -1000.0f;         // DGL zero-mask emulation
    unsigned pos = g_off[d] + atomicAdd(&g_cnt2[d], 1u);
    g_esrc[pos] = s;
    g_eval[pos] = e;
}

// ---- aggregate: warp per dst; softmax + weighted sum, single write ----
__global__ __launch_bounds__(256) void aggregate_kernel(float* __restrict__ out) {
    int d    = (blockIdx.x * blockDim.x + threadIdx.x) >> 5;
    int lane = threadIdx.x & 31;
    if (d >= NWORDS) return;
    int b = (int)g_off[d], eend = (int)g_off[d + 1];

    float mx = -1e30f;
    for (int i = b + lane; i < eend; i += 32) mx = fmaxf(mx, g_eval[i]);
#pragma unroll
    for (int o = 16; o > 0; o >>= 1)
        mx = fmaxf(mx, __shfl_xor_sync(0xffffffffu, mx, o));

    float4 acc = make_float4(0.f, 0.f, 0.f, 0.f);
    float denom = 0.f;
    int i = b;
    for (; i + 3 < eend; i += 4) {
        float e0 = g_eval[i],     e1 = g_eval[i + 1];
        float e2 = g_eval[i + 2], e3 = g_eval[i + 3];
        int   s0 = g_esrc[i],     s1 = g_esrc[i + 1];
        int   s2 = g_esrc[i + 2], s3 = g_esrc[i + 3];
        float4 z0 = *(const float4*)&g_z[(size_t)s0 * OUT_DIM + lane * 4];
        float4 z1 = *(const float4*)&g_z[(size_t)s1 * OUT_DIM + lane * 4];
        float4 z2 = *(const float4*)&g_z[(size_t)s2 * OUT_DIM + lane * 4];
        float4 z3 = *(const float4*)&g_z[(size_t)s3 * OUT_DIM + lane * 4];
        float x0 = __expf(e0 - mx), x1 = __expf(e1 - mx);
        float x2 = __expf(e2 - mx), x3 = __expf(e3 - mx);
        denom += (x0 + x1) + (x2 + x3);
        acc.x += x0 * z0.x + x1 * z1.x + x2 * z2.x + x3 * z3.x;
        acc.y += x0 * z0.y + x1 * z1.y + x2 * z2.y + x3 * z3.y;
        acc.z += x0 * z0.z + x1 * z1.z + x2 * z2.z + x3 * z3.z;
        acc.w += x0 * z0.w + x1 * z1.w + x2 * z2.w + x3 * z3.w;
    }
    for (; i < eend; i++) {
        float e0 = g_eval[i];
        int   s0 = g_esrc[i];
        float4 z0 = *(const float4*)&g_z[(size_t)s0 * OUT_DIM + lane * 4];
        float x0 = __expf(e0 - mx);
        denom += x0;
        acc.x += x0 * z0.x; acc.y += x0 * z0.y;
        acc.z += x0 * z0.z; acc.w += x0 * z0.w;
    }
    float inv = (eend > b) ? 1.0f / denom : 0.0f;
    *(float4*)&out[(size_t)d * OUT_DIM + lane * 4] =
        make_float4(acc.x * inv, acc.y * inv, acc.z * inv, acc.w * inv);
}

extern "C" void kernel_launch(void* const* d_in, const int* in_sizes, int n_in,
                              void* d_out, int out_size) {
    const float* h   = (const float*)d_in[0];
    const int*   src = (const int*)d_in[1];
    const int*   dst = (const int*)d_in[2];
    const float* Wfc = (const float*)d_in[3];
    const float* Wa  = (const float*)d_in[4];
    float* out = (float*)d_out;

    int M = in_sizes[0] / IN_DIM;   // 100000
    int E = in_sizes[1];            // 500000

    init_kernel<<<(NMAX + 255) / 256, 256>>>(Wfc, M);
    gemm_mma<<<(M + 127) / 128, 256>>>(h, Wa, M);
    hist_kernel<<<(E + 8 * 256 - 1) / (8 * 256), 256>>>(dst, E);
    scan_part1<<<SCAN_BLOCKS, 1024>>>();
    scan_part3<<<SCAN_BLOCKS, 1024>>>();
    build_kernel<<<(E + 255) / 256, 256>>>(src, dst, E);
    aggregate_kernel<<<((NWORDS * 32) + 255) / 256, 256>>>(out);
}

// round 11
// speedup vs baseline: 1.3914x; 1.0720x over previous
#include <cuda_runtime.h>
#include <cuda_bf16.h>
#include <cstdint>

#define NMAX 100000
#define NWORDS 50000
#define EMAX 500000
#define IN_DIM 256
#define OUT_DIM 128

// ---- scratch (static device globals; no allocation) ----
__device__ float    g_z[(size_t)NMAX * OUT_DIM];   // fc output z [N,128]
__device__ float    g_s1[NMAX];                    // z . a1
__device__ float    g_s2[NMAX];                    // z . a2
__device__ unsigned g_cnt[NWORDS];                 // per-dst edge counts
__device__ unsigned g_cnt2[NWORDS];                // scatter cursors
__device__ unsigned g_off[NWORDS + 1];             // CSR offsets
__device__ int      g_esrc[EMAX];                  // grouped edge src ids
__device__ float    g_eval[EMAX];                  // grouped edge scores
// pre-split B in swizzled tile layout: [kchunk][128 rows x 64 B]
__device__ __align__(16) uint8_t g_bhi[8 * 8192];
__device__ __align__(16) uint8_t g_blo[8 * 8192];

#define SCAN_BLOCKS ((NWORDS + 1023) / 1024)       // 49
__device__ unsigned g_bsum[SCAN_BLOCKS];

__device__ __forceinline__ uint32_t smem_u32(const void* p) {
    uint32_t a;
    asm("{ .reg .u64 t; cvta.to.shared.u64 t, %1; cvt.u32.u64 %0, t; }" : "=r"(a) : "l"(p));
    return a;
}
__device__ __forceinline__ void ldm_x4(uint32_t* r, uint32_t addr) {
    asm volatile("ldmatrix.sync.aligned.m8n8.x4.shared.b16 {%0,%1,%2,%3}, [%4];"
                 : "=r"(r[0]), "=r"(r[1]), "=r"(r[2]), "=r"(r[3]) : "r"(addr));
}
__device__ __forceinline__ void mma_bf16(float* c, const uint32_t* a, const uint32_t* b) {
    asm volatile(
        "mma.sync.aligned.m16n8k16.row.col.f32.bf16.bf16.f32 "
        "{%0,%1,%2,%3}, {%4,%5,%6,%7}, {%8,%9}, {%0,%1,%2,%3};"
        : "+f"(c[0]), "+f"(c[1]), "+f"(c[2]), "+f"(c[3])
        : "r"(a[0]), "r"(a[1]), "r"(a[2]), "r"(a[3]), "r"(b[0]), "r"(b[1]));
}
__device__ __forceinline__ uint32_t pack2(float a, float b) {
    __nv_bfloat162 t = __floats2bfloat162_rn(a, b);
    return *reinterpret_cast<uint32_t*>(&t);
}
// tile byte offset: row pitch 64B (32 bf16), 16B chunks xor-swizzled
__device__ __forceinline__ uint32_t tile_off(uint32_t row, uint32_t chunk) {
    return row * 64u + ((chunk ^ ((row >> 1) & 3u)) << 4);
}

// ---- init counters + score accumulators + one-time B split-convert ----
__global__ __launch_bounds__(256) void init_kernel(const float* __restrict__ B, int M) {
    int i = blockIdx.x * blockDim.x + threadIdx.x;
    if (i < NWORDS) { g_cnt[i] = 0u; g_cnt2[i] = 0u; }
    if (i < M) { g_s1[i] = 0.0f; g_s2[i] = 0.0f; }
    if (i < 128 * 256) {
        int row = i >> 8, col = i & 255;
        int kc = col >> 5, c = col & 31;
        float v = B[i];
        __nv_bfloat16 hi = __float2bfloat16(v);
        __nv_bfloat16 lo = __float2bfloat16(v - __bfloat162float(hi));
        uint32_t off = (uint32_t)kc * 8192u + tile_off((uint32_t)row, (uint32_t)(c >> 3)) + (c & 7) * 2;
        *(__nv_bfloat16*)(g_bhi + off) = hi;
        *(__nv_bfloat16*)(g_blo + off) = lo;
    }
}

// ==========================================================================
// bf16 split-GEMM via mma.sync (hh + hl + lh), fused s1/s2 epilogue.
// ==========================================================================
__global__ void __launch_bounds__(256, 2)
gemm_mma(const float* __restrict__ A, const float* __restrict__ Wa, int M)
{
    __shared__ __align__(128) uint8_t sAhi[128 * 64];
    __shared__ __align__(128) uint8_t sAlo[128 * 64];
    __shared__ __align__(128) uint8_t sBhi[128 * 64];
    __shared__ __align__(128) uint8_t sBlo[128 * 64];

    const int tid  = threadIdx.x;
    const int lane = tid & 31;
    const int w    = tid >> 5;
    const int wm   = w & 3;
    const int wn   = w >> 2;
    const int block_m = blockIdx.x * 128;
    int rows_valid = M - block_m; if (rows_valid > 128) rows_valid = 128;

    const uint32_t uAhi = smem_u32(sAhi), uAlo = smem_u32(sAlo);
    const uint32_t uBhi = smem_u32(sBhi), uBlo = smem_u32(sBlo);

    const uint32_t a_row  = wm * 32u + (lane & 15);
    const uint32_t a_half = (uint32_t)lane >> 4;
    const uint32_t a_sw   = (a_row >> 1) & 3u;
    const uint32_t b_row  = wn * 64u + (lane & 7) + (((uint32_t)lane >> 4) << 3);
    const uint32_t b_half = ((uint32_t)lane >> 3) & 1u;
    const uint32_t b_sw   = (b_row >> 1) & 3u;

    const int r0 = tid >> 2,         c0 = tid & 3;
    const int r1 = (tid + 256) >> 2, c1 = (tid + 256) & 3;
    const uint32_t doff0 = tile_off((uint32_t)r0, (uint32_t)c0);
    const uint32_t doff1 = tile_off((uint32_t)r1, (uint32_t)c1);

    float acc[2][8][4];
#pragma unroll
    for (int i = 0; i < 2; i++)
#pragma unroll
        for (int j = 0; j < 8; j++)
#pragma unroll
            for (int r = 0; r < 4; r++) acc[i][j][r] = 0.0f;

    float4 pv[4];
    {
        pv[0] = pv[1] = pv[2] = pv[3] = make_float4(0.f, 0.f, 0.f, 0.f);
        if (r0 < rows_valid) {
            const float* p = &A[(size_t)(block_m + r0) * IN_DIM + c0 * 8];
            pv[0] = *(const float4*)p; pv[1] = *(const float4*)(p + 4);
        }
        if (r1 < rows_valid) {
            const float* p = &A[(size_t)(block_m + r1) * IN_DIM + c1 * 8];
            pv[2] = *(const float4*)p; pv[3] = *(const float4*)(p + 4);
        }
    }

    for (int kc = 0; kc < IN_DIM / 32; kc++) {
#pragma unroll
        for (int it = 0; it < 2; it++) {
            float4 v0 = pv[it * 2], v1 = pv[it * 2 + 1];
            uint32_t h0 = pack2(v0.x, v0.y), h1 = pack2(v0.z, v0.w);
            uint32_t h2 = pack2(v1.x, v1.y), h3 = pack2(v1.z, v1.w);
            __nv_bfloat162* q;
            q = (__nv_bfloat162*)&h0;
            uint32_t l0 = pack2(v0.x - __bfloat162float(q->x), v0.y - __bfloat162float(q->y));
            q = (__nv_bfloat162*)&h1;
            uint32_t l1 = pack2(v0.z - __bfloat162float(q->x), v0.w - __bfloat162float(q->y));
            q = (__nv_bfloat162*)&h2;
            uint32_t l2 = pack2(v1.x - __bfloat162float(q->x), v1.y - __bfloat162float(q->y));
            q = (__nv_bfloat162*)&h3;
            uint32_t l3 = pack2(v1.z - __bfloat162float(q->x), v1.w - __bfloat162float(q->y));
            uint32_t doff = it ? doff1 : doff0;
            *(uint4*)(sAhi + doff) = make_uint4(h0, h1, h2, h3);
            *(uint4*)(sAlo + doff) = make_uint4(l0, l1, l2, l3);
        }
        {
            const uint4* bh = (const uint4*)(g_bhi + kc * 8192);
            const uint4* bl = (const uint4*)(g_blo + kc * 8192);
            uint4* dh = (uint4*)sBhi;
            uint4* dl = (uint4*)sBlo;
            dh[tid]       = bh[tid];
            dh[tid + 256] = bh[tid + 256];
            dl[tid]       = bl[tid];
            dl[tid + 256] = bl[tid + 256];
        }
        __syncthreads();

        if (kc + 1 < IN_DIM / 32) {
            const int k0n = (kc + 1) * 32;
            pv[0] = pv[1] = pv[2] = pv[3] = make_float4(0.f, 0.f, 0.f, 0.f);
            if (r0 < rows_valid) {
                const float* p = &A[(size_t)(block_m + r0) * IN_DIM + k0n + c0 * 8];
                pv[0] = *(const float4*)p; pv[1] = *(const float4*)(p + 4);
            }
            if (r1 < rows_valid) {
                const float* p = &A[(size_t)(block_m + r1) * IN_DIM + k0n + c1 * 8];
                pv[2] = *(const float4*)p; pv[3] = *(const float4*)(p + 4);
            }
        }

#pragma unroll
        for (int ks = 0; ks < 2; ks++) {
            uint32_t ahi[2][4], alo[2][4], bb[4][4];
#pragma unroll
            for (int i = 0; i < 2; i++) {
                uint32_t row = a_row + i * 16u;
                uint32_t chunk = (uint32_t)(ks * 2) + a_half;
                uint32_t o = row * 64u + ((chunk ^ a_sw) << 4);
                ldm_x4(ahi[i], uAhi + o);
                ldm_x4(alo[i], uAlo + o);
            }
#pragma unroll
            for (int j = 0; j < 4; j++) {
                uint32_t row = b_row + j * 16u;
                uint32_t chunk = (uint32_t)(ks * 2) + b_half;
                uint32_t o = row * 64u + ((chunk ^ b_sw) << 4);
                ldm_x4(bb[j], uBhi + o);
            }
#pragma unroll
            for (int i = 0; i < 2; i++)
#pragma unroll
                for (int jf = 0; jf < 8; jf++) {
                    mma_bf16(acc[i][jf], ahi[i], &bb[jf >> 1][(jf & 1) * 2]);
                    mma_bf16(acc[i][jf], alo[i], &bb[jf >> 1][(jf & 1) * 2]);
                }
#pragma unroll
            for (int j = 0; j < 4; j++) {
                uint32_t row = b_row + j * 16u;
                uint32_t chunk = (uint32_t)(ks * 2) + b_half;
                uint32_t o = row * 64u + ((chunk ^ b_sw) << 4);
                ldm_x4(bb[j], uBlo + o);
            }
#pragma unroll
            for (int i = 0; i < 2; i++)
#pragma unroll
                for (int jf = 0; jf < 8; jf++)
                    mma_bf16(acc[i][jf], ahi[i], &bb[jf >> 1][(jf & 1) * 2]);
        }
        __syncthreads();
    }

    float rs1[4] = {0.f, 0.f, 0.f, 0.f}, rs2[4] = {0.f, 0.f, 0.f, 0.f};
#pragma unroll
    for (int i = 0; i < 2; i++)
#pragma unroll
        for (int jf = 0; jf < 8; jf++) {
            int n0 = wn * 64 + jf * 8 + (lane & 3) * 2;
            float a1x = __ldg(&Wa[n0]),            a1y = __ldg(&Wa[n0 + 1]);
            float a2x = __ldg(&Wa[OUT_DIM + n0]),  a2y = __ldg(&Wa[OUT_DIM + n0 + 1]);
#pragma unroll
            for (int hh = 0; hh < 2; hh++) {
                float v0 = acc[i][jf][hh * 2], v1 = acc[i][jf][hh * 2 + 1];
                int m = block_m + wm * 32 + i * 16 + hh * 8 + (lane >> 2);
                if (m < M)
                    *(float2*)&g_z[(size_t)m * OUT_DIM + n0] = make_float2(v0, v1);
                rs1[i * 2 + hh] += v0 * a1x + v1 * a1y;
                rs2[i * 2 + hh] += v0 * a2x + v1 * a2y;
            }
        }
#pragma unroll
    for (int k = 0; k < 4; k++) {
        rs1[k] += __shfl_xor_sync(0xffffffffu, rs1[k], 1);
        rs1[k] += __shfl_xor_sync(0xffffffffu, rs1[k], 2);
        rs2[k] += __shfl_xor_sync(0xffffffffu, rs2[k], 1);
        rs2[k] += __shfl_xor_sync(0xffffffffu, rs2[k], 2);
    }
    if ((lane & 3) == 0) {
#pragma unroll
        for (int k = 0; k < 4; k++) {
            int m = block_m + wm * 32 + (k >> 1) * 16 + (k & 1) * 8 + (lane >> 2);
            if (m < M) {
                atomicAdd(&g_s1[m], rs1[k]);
                atomicAdd(&g_s2[m], rs2[k]);
            }
        }
    }
}

// ---- histogram of dst: 8 edges per thread (vectorized, MLP=2x int4) ----
__global__ __launch_bounds__(256) void hist_kernel(const int* __restrict__ dst, int E) {
    int base = (blockIdx.x * blockDim.x + threadIdx.x) * 8;
    if (base + 8 <= E) {
        int4 d0 = *(const int4*)&dst[base];
        int4 d1 = *(const int4*)&dst[base + 4];
        atomicAdd(&g_cnt[d0.x], 1u); atomicAdd(&g_cnt[d0.y], 1u);
        atomicAdd(&g_cnt[d0.z], 1u); atomicAdd(&g_cnt[d0.w], 1u);
        atomicAdd(&g_cnt[d1.x], 1u); atomicAdd(&g_cnt[d1.y], 1u);
        atomicAdd(&g_cnt[d1.z], 1u); atomicAdd(&g_cnt[d1.w], 1u);
    } else {
        for (int i = base; i < E; i++) atomicAdd(&g_cnt[dst[i]], 1u);
    }
}

// ---- scan phase 1: per-block tile reduction (coalesced) ----
__global__ __launch_bounds__(1024) void scan_part1() {
    __shared__ unsigned ws[32];
    const int tid = threadIdx.x, lane = tid & 31, wid = tid >> 5;
    int i = blockIdx.x * 1024 + tid;
    unsigned x = (i < NWORDS) ? g_cnt[i] : 0u;
#pragma unroll
    for (int o = 16; o > 0; o >>= 1) x += __shfl_xor_sync(0xffffffffu, x, o);
    if (lane == 0) ws[wid] = x;
    __syncthreads();
    if (wid == 0) {
        unsigned s = ws[lane];
#pragma unroll
        for (int o = 16; o > 0; o >>= 1) s += __shfl_xor_sync(0xffffffffu, s, o);
        if (lane == 0) g_bsum[blockIdx.x] = s;
    }
}

// ---- scan phase 2 (fused): each block scans block sums + its tile ----
__global__ __launch_bounds__(1024) void scan_part3() {
    __shared__ unsigned ws[32];
    __shared__ unsigned s_boff;
    const int tid = threadIdx.x, lane = tid & 31, wid = tid >> 5;

    if (wid == 0) {
        unsigned acc = 0u;
#pragma unroll
        for (int seg = 0; seg < (SCAN_BLOCKS + 31) / 32; seg++) {
            int j = seg * 32 + lane;
            unsigned v = (j < SCAN_BLOCKS) ? g_bsum[j] : 0u;
            unsigned inc = v;
#pragma unroll
            for (int o = 1; o < 32; o <<= 1) {
                unsigned y = __shfl_up_sync(0xffffffffu, inc, o);
                if (lane >= o) inc += y;
            }
            if (j == (int)blockIdx.x) s_boff = acc + inc - v;
            acc += __shfl_sync(0xffffffffu, inc, 31);
        }
    }

    int i = blockIdx.x * 1024 + tid;
    unsigned x = (i < NWORDS) ? g_cnt[i] : 0u;
    unsigned inc = x;
#pragma unroll
    for (int o = 1; o < 32; o <<= 1) {
        unsigned y = __shfl_up_sync(0xffffffffu, inc, o);
        if (lane >= o) inc += y;
    }
    if (lane == 31) ws[wid] = inc;
    __syncthreads();
    if (wid == 0) {
        unsigned s = ws[lane];
#pragma unroll
        for (int o = 1; o < 32; o <<= 1) {
            unsigned y = __shfl_up_sync(0xffffffffu, s, o);
            if (lane >= o) s += y;
        }
        ws[lane] = s;
    }
    __syncthreads();
    unsigned val = inc + (wid > 0 ? ws[wid - 1] : 0u) + s_boff;
    if (i < NWORDS) g_off[i + 1] = val;
    if (i == 0) g_off[0] = 0u;
}

// ---- build grouped edge arrays: 1 edge/thread (occupancy hides latency) ----
__global__ __launch_bounds__(256) void build_kernel(
    const int* __restrict__ src, const int* __restrict__ dst, int E)
{
    int i = blockIdx.x * blockDim.x + threadIdx.x;
    if (i >= E) return;
    int s = src[i], d = dst[i];
    float e = g_s1[s] + g_s2[d];
    e = (e > 0.0f) ? e : 0.01f * e;      // leaky_relu(0.01)
    if (e == 0.0f) e = -1000.0f;         // DGL zero-mask emulation
    unsigned pos = g_off[d] + atomicAdd(&g_cnt2[d], 1u);
    g_esrc[pos] = s;
    g_eval[pos] = e;
}

// ---- aggregate: warp per dst; softmax + weighted sum, single write ----
__global__ __launch_bounds__(256) void aggregate_kernel(float* __restrict__ out) {
    int d    = (blockIdx.x * blockDim.x + threadIdx.x) >> 5;
    int lane = threadIdx.x & 31;
    if (d >= NWORDS) return;
    int b = (int)g_off[d], eend = (int)g_off[d + 1];

    float mx = -1e30f;
    for (int i = b + lane; i < eend; i += 32) mx = fmaxf(mx, g_eval[i]);
#pragma unroll
    for (int o = 16; o > 0; o >>= 1)
        mx = fmaxf(mx, __shfl_xor_sync(0xffffffffu, mx, o));

    float4 acc = make_float4(0.f, 0.f, 0.f, 0.f);
    float denom = 0.f;
    int i = b;
    for (; i + 3 < eend; i += 4) {
        float e0 = g_eval[i],     e1 = g_eval[i + 1];
        float e2 = g_eval[i + 2], e3 = g_eval[i + 3];
        int   s0 = g_esrc[i],     s1 = g_esrc[i + 1];
        int   s2 = g_esrc[i + 2], s3 = g_esrc[i + 3];
        float4 z0 = *(const float4*)&g_z[(size_t)s0 * OUT_DIM + lane * 4];
        float4 z1 = *(const float4*)&g_z[(size_t)s1 * OUT_DIM + lane * 4];
        float4 z2 = *(const float4*)&g_z[(size_t)s2 * OUT_DIM + lane * 4];
        float4 z3 = *(const float4*)&g_z[(size_t)s3 * OUT_DIM + lane * 4];
        float x0 = __expf(e0 - mx), x1 = __expf(e1 - mx);
        float x2 = __expf(e2 - mx), x3 = __expf(e3 - mx);
        denom += (x0 + x1) + (x2 + x3);
        acc.x += x0 * z0.x + x1 * z1.x + x2 * z2.x + x3 * z3.x;
        acc.y += x0 * z0.y + x1 * z1.y + x2 * z2.y + x3 * z3.y;
        acc.z += x0 * z0.z + x1 * z1.z + x2 * z2.z + x3 * z3.z;
        acc.w += x0 * z0.w + x1 * z1.w + x2 * z2.w + x3 * z3.w;
    }
    for (; i < eend; i++) {
        float e0 = g_eval[i];
        int   s0 = g_esrc[i];
        float4 z0 = *(const float4*)&g_z[(size_t)s0 * OUT_DIM + lane * 4];
        float x0 = __expf(e0 - mx);
        denom += x0;
        acc.x += x0 * z0.x; acc.y += x0 * z0.y;
        acc.z += x0 * z0.z; acc.w += x0 * z0.w;
    }
    float inv = (eend > b) ? 1.0f / denom : 0.0f;
    *(float4*)&out[(size_t)d * OUT_DIM + lane * 4] =
        make_float4(acc.x * inv, acc.y * inv, acc.z * inv, acc.w * inv);
}

extern "C" void kernel_launch(void* const* d_in, const int* in_sizes, int n_in,
                              void* d_out, int out_size) {
    const float* h   = (const float*)d_in[0];
    const int*   src = (const int*)d_in[1];
    const int*   dst = (const int*)d_in[2];
    const float* Wfc = (const float*)d_in[3];
    const float* Wa  = (const float*)d_in[4];
    float* out = (float*)d_out;

    int M = in_sizes[0] / IN_DIM;   // 100000
    int E = in_sizes[1];            // 500000

    // fork-join: hist/scan chain (depends only on init+dst) overlaps the GEMM
    cudaStream_t s2;
    cudaStreamCreateWithFlags(&s2, cudaStreamNonBlocking);
    cudaEvent_t ev_fork, ev_join;
    cudaEventCreateWithFlags(&ev_fork, cudaEventDisableTiming);
    cudaEventCreateWithFlags(&ev_join, cudaEventDisableTiming);

    init_kernel<<<(NMAX + 255) / 256, 256>>>(Wfc, M);
    cudaEventRecord(ev_fork, 0);

    // side stream: histogram + scan
    cudaStreamWaitEvent(s2, ev_fork, 0);
    hist_kernel<<<(E + 8 * 256 - 1) / (8 * 256), 256, 0, s2>>>(dst, E);
    scan_part1<<<SCAN_BLOCKS, 1024, 0, s2>>>();
    scan_part3<<<SCAN_BLOCKS, 1024, 0, s2>>>();
    cudaEventRecord(ev_join, s2);

    // main stream: GEMM (bulk of the work)
    gemm_mma<<<(M + 127) / 128, 256>>>(h, Wa, M);

    cudaStreamWaitEvent(0, ev_join, 0);
    build_kernel<<<(E + 255) / 256, 256>>>(src, dst, E);
    aggregate_kernel<<<((NWORDS * 32) + 255) / 256, 256>>>(out);

    cudaEventDestroy(ev_fork);
    cudaEventDestroy(ev_join);
    cudaStreamDestroy(s2);
}